// round 11
// baseline (speedup 1.0000x reference)
#include <cuda_runtime.h>
#include <cuda_bf16.h>

// BackwardRPM: 16384 independent 200-step solves.
//   per step: h = tanh(u@W1 + b1) (64,), grad6 = C@h + d - s, u = clip(u - 0.01*grad6)
// with A = R[:, :6]^T R (6x40), C = A W2^T (6x64), d = A@b2, s = A@spec.
//
// R10 = R9 with the s_cp cooperative-fill indexing bug fixed (flat decompose
// t = ps*48 + i*8 + s; R9 left s_cp[1][4..5][*] uninitialized).
//  - b1p + the p=2,3 slices of cp live in shared memory (16 LDS.64/thread-step)
//  - launch_bounds(128,4): 128-reg cap -> 4 CTAs -> 16 warps/SM (4/SMSP)
//  - everything else identical to R2 (best passing: 145.9us).

#define STEPS 200
#define LR 0.01f
#define BATCH 16384
#define HID 64
#define PROJ 8
#define NSPEC 40

typedef unsigned long long u64x;

__device__ float g_A[6 * NSPEC];   // A = R6^T R
__device__ float g_C[6 * HID];     // C = A W2^T
__device__ float g_d[6];           // d = A b2

__global__ void precompute_kernel(const float* __restrict__ W2,
                                  const float* __restrict__ b2,
                                  const float* __restrict__ R) {
    __shared__ float sA[6 * NSPEC];
    int tid = threadIdx.x;

    for (int t = tid; t < 6 * NSPEC; t += blockDim.x) {
        int i = t / NSPEC, k = t % NSPEC;
        float acc = 0.0f;
#pragma unroll
        for (int p = 0; p < PROJ; ++p)
            acc = fmaf(R[p * NSPEC + i], R[p * NSPEC + k], acc);
        sA[t] = acc;
        g_A[t] = acc;
    }
    __syncthreads();

    for (int t = tid; t < 6 * HID; t += blockDim.x) {
        int i = t / HID, j = t % HID;
        float acc = 0.0f;
#pragma unroll
        for (int k = 0; k < NSPEC; ++k)
            acc = fmaf(sA[i * NSPEC + k], W2[j * NSPEC + k], acc);
        g_C[t] = acc;
    }

    if (tid < 6) {
        float acc = 0.0f;
#pragma unroll
        for (int k = 0; k < NSPEC; ++k)
            acc = fmaf(sA[tid * NSPEC + k], b2[k], acc);
        g_d[tid] = acc;
    }
}

// ---- f32x2 helpers ----
__device__ __forceinline__ u64x pack2(float lo, float hi) {
    u64x r; asm("mov.b64 %0, {%1, %2};" : "=l"(r) : "f"(lo), "f"(hi)); return r;
}
__device__ __forceinline__ void unpack2(u64x v, float& lo, float& hi) {
    asm("mov.b64 {%0, %1}, %2;" : "=f"(lo), "=f"(hi) : "l"(v));
}
__device__ __forceinline__ u64x fma2(u64x a, u64x b, u64x c) {
    u64x d; asm("fma.rn.f32x2 %0, %1, %2, %3;" : "=l"(d) : "l"(a), "l"(b), "l"(c)); return d;
}
__device__ __forceinline__ u64x add2(u64x a, u64x b) {
    u64x d; asm("add.rn.f32x2 %0, %1, %2;" : "=l"(d) : "l"(a), "l"(b)); return d;
}
__device__ __forceinline__ float tanh_fast(float x) {
    float y; asm("tanh.approx.f32 %0, %1;" : "=f"(y) : "f"(x)); return y;
}

__global__ void __launch_bounds__(128, 4)
solve_kernel(const float* __restrict__ spectrum,
             const float* __restrict__ W1,
             const float* __restrict__ b1,
             float* __restrict__ out) {
    // smem-resident weight slices, indexed by sub (8 distinct 8B words ->
    // conflict-free 4-way broadcast within a warp).
    __shared__ u64x s_cp[2][6][8];   // p = 2,3 slices of cp
    __shared__ u64x s_b1[4][8];      // b1 pairs, all p

    const int tid = threadIdx.x;
    const int gtid = blockIdx.x * blockDim.x + tid;
    const int sample = gtid >> 3;       // 8 lanes per sample
    const int sub = gtid & 7;           // hidden-dim slice

    // Cooperative smem fill: 96 s_cp entries as t = ps*48 + i*8 + s.
    if (tid < 96) {
        int ps = tid / 48;              // 0..1  (p-2)
        int rem = tid - ps * 48;
        int i = rem >> 3;               // 0..5
        int s = rem & 7;
        int j0 = s + 16 * (ps + 2);
        s_cp[ps][i][s] = pack2(g_C[i * HID + j0], g_C[i * HID + j0 + 8]);
    } else {
        int t = tid - 96;               // 0..31 -> s_b1
        int p = t >> 3, s = t & 7;
        int j0 = s + 16 * p;
        s_b1[p][s] = pack2(b1[j0], b1[j0 + 8]);
    }
    __syncthreads();

    // Register-resident weights: w1p all 4 slices, cp slices p=0,1 only.
    u64x w1p[6][4];
    u64x cpr[6][2];
#pragma unroll
    for (int p = 0; p < 4; ++p) {
        int j0 = sub + 16 * p;
        int j1 = j0 + 8;
#pragma unroll
        for (int i = 0; i < 6; ++i)
            w1p[i][p] = pack2(__ldg(&W1[i * HID + j0]), __ldg(&W1[i * HID + j1]));
    }
#pragma unroll
    for (int p = 0; p < 2; ++p) {
        int j0 = sub + 16 * p;
        int j1 = j0 + 8;
#pragma unroll
        for (int i = 0; i < 6; ++i)
            cpr[i][p] = pack2(g_C[i * HID + j0], g_C[i * HID + j1]);
    }

    // base[i] = d[i] - (A @ spec)[i]
    const float* sp = spectrum + sample * NSPEC;
    float base[6];
#pragma unroll
    for (int i = 0; i < 6; ++i) {
        float acc = 0.0f;
#pragma unroll
        for (int k = 0; k < NSPEC; ++k)
            acc = fmaf(g_A[i * NSPEC + k], __ldg(&sp[k]), acc);
        base[i] = g_d[i] - acc;
    }

    // u permanently packed as (u, u).
    u64x uq[6];
#pragma unroll
    for (int i = 0; i < 6; ++i) uq[i] = pack2(0.5f, 0.5f);

#pragma unroll 1
    for (int t = 0; t < STEPS; ++t) {
        u64x g2[6];
#pragma unroll
        for (int i = 0; i < 6; ++i) g2[i] = 0ull;

#pragma unroll
        for (int p = 0; p < 4; ++p) {
            u64x v = s_b1[p][sub];
#pragma unroll
            for (int i = 0; i < 6; ++i) v = fma2(uq[i], w1p[i][p], v);
            float v0, v1;
            unpack2(v, v0, v1);
            u64x hp = pack2(tanh_fast(v0), tanh_fast(v1));
            if (p < 2) {
#pragma unroll
                for (int i = 0; i < 6; ++i) g2[i] = fma2(hp, cpr[i][p], g2[i]);
            } else {
#pragma unroll
                for (int i = 0; i < 6; ++i) g2[i] = fma2(hp, s_cp[p - 2][i][sub], g2[i]);
            }
        }

        // collapse pair halves -> 6 scalars, pack into 3 f32x2
        float gr[6];
#pragma unroll
        for (int i = 0; i < 6; ++i) {
            float a, b;
            unpack2(g2[i], a, b);
            gr[i] = a + b;
        }
        u64x r0 = pack2(gr[0], gr[1]);
        u64x r1 = pack2(gr[2], gr[3]);
        u64x r2 = pack2(gr[4], gr[5]);
#pragma unroll
        for (int d = 1; d < 8; d <<= 1) {
            r0 = add2(r0, __shfl_xor_sync(0xffffffffu, r0, d));
            r1 = add2(r1, __shfl_xor_sync(0xffffffffu, r1, d));
            r2 = add2(r2, __shfl_xor_sync(0xffffffffu, r2, d));
        }
        unpack2(r0, gr[0], gr[1]);
        unpack2(r1, gr[2], gr[3]);
        unpack2(r2, gr[4], gr[5]);

#pragma unroll
        for (int i = 0; i < 6; ++i) {
            float ulo, uhi;
            unpack2(uq[i], ulo, uhi);
            (void)uhi;
            float un = fmaf(-LR, gr[i] + base[i], ulo);
            un = fminf(1.0f, fmaxf(0.0f, un));
            uq[i] = pack2(un, un);
        }
    }

    if (sub == 0) {
        float r, hi;
#pragma unroll
        for (int i = 0; i < 6; ++i) {
            unpack2(uq[i], r, hi);
            (void)hi;
            out[sample * 6 + i] = r;
        }
    }
}

extern "C" void kernel_launch(void* const* d_in, const int* in_sizes, int n_in,
                              void* d_out, int out_size) {
    // metadata order: spectrum, W1, b1, W2, b2, R
    const float* spectrum = (const float*)d_in[0];
    const float* W1 = (const float*)d_in[1];
    const float* b1 = (const float*)d_in[2];
    const float* W2 = (const float*)d_in[3];
    const float* b2 = (const float*)d_in[4];
    const float* R  = (const float*)d_in[5];
    float* out = (float*)d_out;

    precompute_kernel<<<1, 256>>>(W2, b2, R);

    const int threads = 128;
    const int total = BATCH * 8;
    solve_kernel<<<total / threads, threads>>>(spectrum, W1, b1, out);
}

// round 12
// speedup vs baseline: 1.1468x; 1.1468x over previous
#include <cuda_runtime.h>
#include <cuda_bf16.h>

// BackwardRPM: 16384 independent 200-step solves.
//   per step: h = tanh(u@W1 + b1) (64,), grad6 = C@h + d - s, u = clip(u - 0.01*grad6)
// with A = R[:, :6]^T R (6x40), C = A W2^T (6x64), d = A@b2, s = A@spec.
//
// R11 = R2 (best passing: 145.9us; 8 lanes/sample, all weights in registers,
// f32x2 math, intrinsic shfl butterfly) + fma-tail trim:
//  - base folded into the g2 init as a precomputed (base/8, 0) pair
//    (division by 8 exact; the 8-lane butterfly restores the full base).
//    Deletes 6 FADD (collapse of base) + 6 FADD (gr+base) per step.
//  - __launch_bounds__(128, 3) pins 3 CTAs/SM (reg cap 170) so the +6
//    baseq registers cannot drop occupancy.

#define STEPS 200
#define LR 0.01f
#define BATCH 16384
#define HID 64
#define PROJ 8
#define NSPEC 40

typedef unsigned long long u64x;

__device__ float g_A[6 * NSPEC];   // A = R6^T R
__device__ float g_C[6 * HID];     // C = A W2^T
__device__ float g_d[6];           // d = A b2

__global__ void precompute_kernel(const float* __restrict__ W2,
                                  const float* __restrict__ b2,
                                  const float* __restrict__ R) {
    __shared__ float sA[6 * NSPEC];
    int tid = threadIdx.x;

    for (int t = tid; t < 6 * NSPEC; t += blockDim.x) {
        int i = t / NSPEC, k = t % NSPEC;
        float acc = 0.0f;
#pragma unroll
        for (int p = 0; p < PROJ; ++p)
            acc = fmaf(R[p * NSPEC + i], R[p * NSPEC + k], acc);
        sA[t] = acc;
        g_A[t] = acc;
    }
    __syncthreads();

    for (int t = tid; t < 6 * HID; t += blockDim.x) {
        int i = t / HID, j = t % HID;
        float acc = 0.0f;
#pragma unroll
        for (int k = 0; k < NSPEC; ++k)
            acc = fmaf(sA[i * NSPEC + k], W2[j * NSPEC + k], acc);
        g_C[t] = acc;
    }

    if (tid < 6) {
        float acc = 0.0f;
#pragma unroll
        for (int k = 0; k < NSPEC; ++k)
            acc = fmaf(sA[tid * NSPEC + k], b2[k], acc);
        g_d[tid] = acc;
    }
}

// ---- f32x2 helpers ----
__device__ __forceinline__ u64x pack2(float lo, float hi) {
    u64x r; asm("mov.b64 %0, {%1, %2};" : "=l"(r) : "f"(lo), "f"(hi)); return r;
}
__device__ __forceinline__ void unpack2(u64x v, float& lo, float& hi) {
    asm("mov.b64 {%0, %1}, %2;" : "=f"(lo), "=f"(hi) : "l"(v));
}
__device__ __forceinline__ u64x fma2(u64x a, u64x b, u64x c) {
    u64x d; asm("fma.rn.f32x2 %0, %1, %2, %3;" : "=l"(d) : "l"(a), "l"(b), "l"(c)); return d;
}
__device__ __forceinline__ u64x add2(u64x a, u64x b) {
    u64x d; asm("add.rn.f32x2 %0, %1, %2;" : "=l"(d) : "l"(a), "l"(b)); return d;
}
__device__ __forceinline__ float tanh_fast(float x) {
    float y; asm("tanh.approx.f32 %0, %1;" : "=f"(y) : "f"(x)); return y;
}

__global__ void __launch_bounds__(128, 3)
solve_kernel(const float* __restrict__ spectrum,
             const float* __restrict__ W1,
             const float* __restrict__ b1,
             float* __restrict__ out) {
    const int gtid = blockIdx.x * blockDim.x + threadIdx.x;
    const int sample = gtid >> 3;       // 8 lanes per sample (grid exact)
    const int sub = gtid & 7;           // hidden-dim slice

    // Weight pairs in registers: pair p covers j0 = sub+16p and j1 = sub+16p+8.
    u64x w1p[6][4];
    u64x cp[6][4];
    u64x b1p[4];
#pragma unroll
    for (int p = 0; p < 4; ++p) {
        int j0 = sub + 16 * p;
        int j1 = j0 + 8;
        b1p[p] = pack2(__ldg(&b1[j0]), __ldg(&b1[j1]));
#pragma unroll
        for (int i = 0; i < 6; ++i) {
            w1p[i][p] = pack2(__ldg(&W1[i * HID + j0]), __ldg(&W1[i * HID + j1]));
            cp[i][p]  = pack2(g_C[i * HID + j0], g_C[i * HID + j1]);
        }
    }

    // baseq[i] = ((d[i] - (A @ spec)[i]) / 8, 0): folded into the g2 init.
    // /8 is exact; the 8-lane butterfly sums 8 copies -> full base.
    const float* sp = spectrum + sample * NSPEC;
    u64x baseq[6];
#pragma unroll
    for (int i = 0; i < 6; ++i) {
        float acc = 0.0f;
#pragma unroll
        for (int k = 0; k < NSPEC; ++k)
            acc = fmaf(g_A[i * NSPEC + k], __ldg(&sp[k]), acc);
        baseq[i] = pack2((g_d[i] - acc) * 0.125f, 0.0f);
    }

    // u permanently packed as (u, u).
    u64x uq[6];
#pragma unroll
    for (int i = 0; i < 6; ++i) uq[i] = pack2(0.5f, 0.5f);

#pragma unroll 1
    for (int t = 0; t < STEPS; ++t) {
        u64x g2[6];
#pragma unroll
        for (int i = 0; i < 6; ++i) g2[i] = baseq[i];

#pragma unroll
        for (int p = 0; p < 4; ++p) {
            u64x v = b1p[p];
#pragma unroll
            for (int i = 0; i < 6; ++i) v = fma2(uq[i], w1p[i][p], v);
            float v0, v1;
            unpack2(v, v0, v1);
            u64x hp = pack2(tanh_fast(v0), tanh_fast(v1));
#pragma unroll
            for (int i = 0; i < 6; ++i) g2[i] = fma2(hp, cp[i][p], g2[i]);
        }

        // collapse pair halves -> 6 scalars (base/8 already included)
        float gr[6];
#pragma unroll
        for (int i = 0; i < 6; ++i) {
            float a, b;
            unpack2(g2[i], a, b);
            gr[i] = a + b;
        }
        u64x r0 = pack2(gr[0], gr[1]);
        u64x r1 = pack2(gr[2], gr[3]);
        u64x r2 = pack2(gr[4], gr[5]);
#pragma unroll
        for (int d = 1; d < 8; d <<= 1) {
            r0 = add2(r0, __shfl_xor_sync(0xffffffffu, r0, d));
            r1 = add2(r1, __shfl_xor_sync(0xffffffffu, r1, d));
            r2 = add2(r2, __shfl_xor_sync(0xffffffffu, r2, d));
        }
        unpack2(r0, gr[0], gr[1]);
        unpack2(r1, gr[2], gr[3]);
        unpack2(r2, gr[4], gr[5]);

#pragma unroll
        for (int i = 0; i < 6; ++i) {
            float ulo, uhi;
            unpack2(uq[i], ulo, uhi);
            (void)uhi;
            float un = fmaf(-LR, gr[i], ulo);   // base already inside gr
            un = fminf(1.0f, fmaxf(0.0f, un));
            uq[i] = pack2(un, un);
        }
    }

    if (sub == 0) {
        float r, hi;
#pragma unroll
        for (int i = 0; i < 6; ++i) {
            unpack2(uq[i], r, hi);
            (void)hi;
            out[sample * 6 + i] = r;
        }
    }
}

extern "C" void kernel_launch(void* const* d_in, const int* in_sizes, int n_in,
                              void* d_out, int out_size) {
    // metadata order: spectrum, W1, b1, W2, b2, R
    const float* spectrum = (const float*)d_in[0];
    const float* W1 = (const float*)d_in[1];
    const float* b1 = (const float*)d_in[2];
    const float* W2 = (const float*)d_in[3];
    const float* b2 = (const float*)d_in[4];
    const float* R  = (const float*)d_in[5];
    float* out = (float*)d_out;

    precompute_kernel<<<1, 256>>>(W2, b2, R);

    const int threads = 128;
    const int total = BATCH * 8;
    solve_kernel<<<total / threads, threads>>>(spectrum, W1, b1, out);
}